// round 2
// baseline (speedup 1.0000x reference)
#include <cuda_runtime.h>
#include <math.h>

#define N_ENT 100000
#define N_REL 64
#define EDIM  64
#define KN    32
#define BSZ   1024
#define SLOPE 0.2f

// Scratch (device globals; no allocation allowed)
__device__ float g_scale[N_ENT];                    // per-row normalization scale (400 KB)
__device__ __align__(16) float g_RwT[EDIM * N_REL]; // [f][r] = sum_e Rn[r][e] * att_w1[f][64+e]

// ---------------------------------------------------------------------------
// Fused prep kernel:
//   blocks [0, 3125): per-row scale of E — 8 threads/row, float4 loads
//   block  3125      : Rn = normalize(R); g_RwT[f][r] = Rn[r]·att_w1[f][64:]
// ---------------------------------------------------------------------------
__global__ void prep_kernel(const float* __restrict__ E,
                            const float* __restrict__ R,
                            const float* __restrict__ att_w1) {
    const int tid = threadIdx.x;  // 256
    if (blockIdx.x < 3125) {
        const int row  = blockIdx.x * 32 + (tid >> 3);
        const int part = tid & 7;
        const float4* Ev = reinterpret_cast<const float4*>(E + row * 64);
        float4 a = Ev[part * 2], b2 = Ev[part * 2 + 1];
        float ss = a.x*a.x + a.y*a.y + a.z*a.z + a.w*a.w
                 + b2.x*b2.x + b2.y*b2.y + b2.z*b2.z + b2.w*b2.w;
        ss += __shfl_xor_sync(0xffffffffu, ss, 4, 8);
        ss += __shfl_xor_sync(0xffffffffu, ss, 2, 8);
        ss += __shfl_xor_sync(0xffffffffu, ss, 1, 8);
        if (part == 0) {
            float n = sqrtf(ss);
            g_scale[row] = (n > 1.0f) ? (1.0f / (n + 1e-7f)) : 1.0f;
        }
        return;
    }
    // ---- prep Rw (single block) ----
    __shared__ float sRn[N_REL * EDIM];
    __shared__ float sScale[N_REL];
    for (int i = tid; i < N_REL * EDIM; i += 256) sRn[i] = R[i];
    __syncthreads();
    if (tid < N_REL) {
        float ss = 0.f;
        for (int e = 0; e < EDIM; e++) { float v = sRn[tid * EDIM + e]; ss += v * v; }
        float n = sqrtf(ss);
        sScale[tid] = (n > 1.0f) ? (1.0f / (n + 1e-7f)) : 1.0f;
    }
    __syncthreads();
    for (int i = tid; i < N_REL * EDIM; i += 256) sRn[i] *= sScale[i >> 6];
    __syncthreads();
    for (int i = tid; i < EDIM * N_REL; i += 256) {
        int f = i >> 6, r = i & 63;
        const float* w = att_w1 + f * 128 + 64;
        float acc = 0.f;
        for (int e = 0; e < EDIM; e++) acc += sRn[r * EDIM + e] * w[e];
        g_RwT[i] = acc;  // [f][r]
    }
}

// ---------------------------------------------------------------------------
// Main kernel: one block per batch element, 256 threads
// ---------------------------------------------------------------------------
__global__ __launch_bounds__(256) void kgan_main_kernel(
    const int*   __restrict__ entity_idx,
    const int*   __restrict__ adj_entity,
    const int*   __restrict__ adj_relation,
    const float* __restrict__ E,
    const float* __restrict__ att_w1,
    const float* __restrict__ att_w2,
    const float* __restrict__ att_w3,
    const float* __restrict__ wx_w,
    const float* __restrict__ wx_b,
    const float* __restrict__ wc_w,
    const float* __restrict__ wc_b,
    float*       __restrict__ out)
{
    __shared__ __align__(16) float sRwT[64 * 64];  // [f][r]
    __shared__ __align__(16) float sW2 [64 * 64];  // att_w2 row-major [g][f]
    __shared__ float sw3[64];
    __shared__ float sh[64], shsum[64], sbh1[64], sbh2[64];
    __shared__ __align__(16) float st1[32 * 64];   // scaled t1 rows [k][f]
    __shared__ int   sEnt1[32], sRel1[32];
    __shared__ float sScale1[32];
    __shared__ float sPa[2 * 128];                 // stage-7 partial dot (two g-halves)
    __shared__ float sE1[64], sE2[64];             // exp(sigmoid(a)) per relation
    __shared__ __align__(16) float2 sAggP2[8 * 32];// per-warp hop2 partial agg
    __shared__ float sSP[8];
    __shared__ float sAgg[64], sV[64];
    __shared__ float sWk[32];

    const int tid  = threadIdx.x;
    const int b    = blockIdx.x;
    const int lane = tid & 31;
    const int warp = tid >> 5;

    // ---- load weight tables into shared ----
    for (int i = tid; i < 4096; i += 256) sRwT[i] = g_RwT[i];
    for (int i = tid; i < 4096; i += 256) sW2[i]  = att_w2[i];
    if (tid < 64) sw3[tid] = att_w3[tid];

    const int eidx = entity_idx[b];
    if (tid < 32) {
        int e1 = adj_entity[eidx * KN + tid];
        sEnt1[tid]   = e1;
        sRel1[tid]   = adj_relation[eidx * KN + tid];
        sScale1[tid] = g_scale[e1];
    }
    if (tid < 64) sh[tid] = E[eidx * 64 + tid] * g_scale[eidx];
    __syncthreads();

    // ---- t1 = scale * E[ent1] (32x64) ----
    for (int i = tid; i < 2048; i += 256) {
        int k = i >> 6, f = i & 63;
        st1[i] = E[sEnt1[k] * 64 + f] * sScale1[k];
    }
    __syncthreads();

    // ---- hsum = t1.sum(axis=0) ----
    if (tid < 64) {
        float s = 0.f;
        #pragma unroll
        for (int k = 0; k < 32; k++) s += st1[k * 64 + tid];
        shsum[tid] = s;
    }
    __syncthreads();

    // ---- bh1 = h @ w1h^T, bh2 = hsum @ w1h^T ----
    if (tid < 128) {
        int f = tid & 63;
        const float*  src = (tid < 64) ? sh : shsum;
        const float4* w   = reinterpret_cast<const float4*>(att_w1 + f * 128);
        float acc = 0.f;
        #pragma unroll
        for (int e4 = 0; e4 < 16; e4++) {
            float4 wv = w[e4];
            acc += wv.x * src[e4 * 4] + wv.y * src[e4 * 4 + 1]
                 + wv.z * src[e4 * 4 + 2] + wv.w * src[e4 * 4 + 3];
        }
        if (tid < 64) sbh1[f] = acc; else sbh2[f] = acc;
    }

    // ---- prefetch hop-2 adjacency + scales into registers ----
    // (independent of stage 7; ~500cyc L2 latency hides behind the FMA burst)
    int   rEi[4], rRi[4];
    float rSc[4];
    #pragma unroll
    for (int j = 0; j < 4; j++) {
        const int base = sEnt1[warp * 4 + j] * KN;
        rEi[j] = adj_entity[base + lane];
        rRi[j] = adj_relation[base + lane];
    }
    #pragma unroll
    for (int j = 0; j < 4; j++) rSc[j] = g_scale[rEi[j]];
    __syncthreads();

    // ---- stage 7: per-relation attention logits (128 tasks x 2 g-halves) ----
    {
        const int task  = tid & 127;          // [0,64): hop1 rel r; [64,128): hop2 rel r
        const int ghalf = tid >> 7;
        const int r     = task & 63;
        const float* bh = (task < 64) ? sbh1 : sbh2;

        float hid[64];
        #pragma unroll
        for (int f = 0; f < 64; f++)
            hid[f] = fmaxf(bh[f] + sRwT[f * 64 + r], 0.0f);

        const float4* w2v = reinterpret_cast<const float4*>(sW2);
        float a = 0.0f;
        const int g0 = ghalf * 32;
        #pragma unroll 2
        for (int g = g0; g < g0 + 32; g++) {
            float acc0 = 0.f, acc1 = 0.f;
            #pragma unroll
            for (int f4 = 0; f4 < 16; f4 += 2) {
                float4 wa = w2v[g * 16 + f4];
                float4 wb = w2v[g * 16 + f4 + 1];
                acc0 += wa.x * hid[f4 * 4]     + wa.y * hid[f4 * 4 + 1]
                      + wa.z * hid[f4 * 4 + 2] + wa.w * hid[f4 * 4 + 3];
                acc1 += wb.x * hid[f4 * 4 + 4] + wb.y * hid[f4 * 4 + 5]
                      + wb.z * hid[f4 * 4 + 6] + wb.w * hid[f4 * 4 + 7];
            }
            a += sw3[g] * fmaxf(acc0 + acc1, 0.0f);
        }
        sPa[ghalf * 128 + task] = a;
    }
    __syncthreads();

    if (tid < 128) {
        float av  = sPa[tid] + sPa[128 + tid];
        float sig = 1.0f / (1.0f + expf(-av));
        float e   = expf(sig);                 // logits in (0,1): no max-sub needed
        if (tid < 64) sE1[tid] = e; else sE2[tid - 64] = e;
    }
    __syncthreads();

    // ---- hop 1: softmax-weighted aggregation over 32 neighbors ----
    if (tid < 32) sWk[tid] = sE1[sRel1[tid]];
    __syncthreads();
    if (tid < 64) {
        float s = 0.f, acc = 0.f;
        #pragma unroll
        for (int k = 0; k < 32; k++) { float w = sWk[k]; s += w; acc += w * st1[k * 64 + tid]; }
        sAgg[tid] = acc / s;
    }
    __syncthreads();
    // v1 = leaky(agg @ wx_w^T + wx_b)
    if (tid < 64) {
        const float4* w = reinterpret_cast<const float4*>(wx_w + tid * 64);
        float acc = wx_b[tid];
        #pragma unroll
        for (int e4 = 0; e4 < 16; e4++) {
            float4 wv = w[e4];
            acc += wv.x * sAgg[e4 * 4]     + wv.y * sAgg[e4 * 4 + 1]
                 + wv.z * sAgg[e4 * 4 + 2] + wv.w * sAgg[e4 * 4 + 3];
        }
        sV[tid] = (acc >= 0.f) ? acc : SLOPE * acc;
    }
    __syncthreads();
    // emb1 = leaky([h, v1] @ wc_w^T + wc_b); also emit h
    if (tid < 64) {
        const float4* w = reinterpret_cast<const float4*>(wc_w + tid * 128);
        float acc = wc_b[tid];
        #pragma unroll
        for (int e4 = 0; e4 < 16; e4++) {
            float4 wv = w[e4];
            acc += wv.x * sh[e4 * 4]     + wv.y * sh[e4 * 4 + 1]
                 + wv.z * sh[e4 * 4 + 2] + wv.w * sh[e4 * 4 + 3];
        }
        #pragma unroll
        for (int e4 = 0; e4 < 16; e4++) {
            float4 wv = w[16 + e4];
            acc += wv.x * sV[e4 * 4]     + wv.y * sV[e4 * 4 + 1]
                 + wv.z * sV[e4 * 4 + 2] + wv.w * sV[e4 * 4 + 3];
        }
        out[b * 192 + 64 + tid]  = (acc >= 0.f) ? acc : SLOPE * acc;
        out[b * 192 + 128 + tid] = sh[tid];
    }

    // ---- hop 2: 1024 neighbors; warp handles n1 in [warp*4, warp*4+4) ----
    // numerator weight = e(rel) * scale(ent);  denominator = sum e(rel) (unscaled)
    float accx = 0.f, accy = 0.f, ssum = 0.f;
    const float2* E2 = reinterpret_cast<const float2*>(E);
    #pragma unroll
    for (int j = 0; j < 4; j++) {
        float en = sE2[rRi[j]];
        ssum += en;
        float wt = en * rSc[j];
        int   ei = rEi[j];
        #pragma unroll 16
        for (int k = 0; k < 32; k++) {
            int   idx = __shfl_sync(0xffffffffu, ei, k);
            float wv  = __shfl_sync(0xffffffffu, wt, k);
            float2 v  = E2[idx * 32 + lane];
            accx += wv * v.x;
            accy += wv * v.y;
        }
    }
    #pragma unroll
    for (int o = 16; o > 0; o >>= 1) ssum += __shfl_xor_sync(0xffffffffu, ssum, o);
    if (lane == 0) sSP[warp] = ssum;
    sAggP2[warp * 32 + lane] = make_float2(accx, accy);
    __syncthreads();

    if (tid < 64) {
        const float* aggp = reinterpret_cast<const float*>(sAggP2);
        float s2 = 0.f;
        #pragma unroll
        for (int w = 0; w < 8; w++) s2 += sSP[w];
        float acc = 0.f;
        #pragma unroll
        for (int w = 0; w < 8; w++) acc += aggp[w * 64 + tid];
        sAgg[tid] = acc / s2;
    }
    __syncthreads();
    // v2 = leaky(agg2 @ wx_w^T + wx_b)
    if (tid < 64) {
        const float4* w = reinterpret_cast<const float4*>(wx_w + tid * 64);
        float acc = wx_b[tid];
        #pragma unroll
        for (int e4 = 0; e4 < 16; e4++) {
            float4 wv = w[e4];
            acc += wv.x * sAgg[e4 * 4]     + wv.y * sAgg[e4 * 4 + 1]
                 + wv.z * sAgg[e4 * 4 + 2] + wv.w * sAgg[e4 * 4 + 3];
        }
        sV[tid] = (acc >= 0.f) ? acc : SLOPE * acc;
    }
    __syncthreads();
    // emb2 = leaky([hsum, v2] @ wc_w^T + wc_b)
    if (tid < 64) {
        const float4* w = reinterpret_cast<const float4*>(wc_w + tid * 128);
        float acc = wc_b[tid];
        #pragma unroll
        for (int e4 = 0; e4 < 16; e4++) {
            float4 wv = w[e4];
            acc += wv.x * shsum[e4 * 4]     + wv.y * shsum[e4 * 4 + 1]
                 + wv.z * shsum[e4 * 4 + 2] + wv.w * shsum[e4 * 4 + 3];
        }
        #pragma unroll
        for (int e4 = 0; e4 < 16; e4++) {
            float4 wv = w[16 + e4];
            acc += wv.x * sV[e4 * 4]     + wv.y * sV[e4 * 4 + 1]
                 + wv.z * sV[e4 * 4 + 2] + wv.w * sV[e4 * 4 + 3];
        }
        out[b * 192 + tid] = (acc >= 0.f) ? acc : SLOPE * acc;
    }
}

extern "C" void kernel_launch(void* const* d_in, const int* in_sizes, int n_in,
                              void* d_out, int out_size) {
    const int*   entity_idx   = (const int*)  d_in[0];
    const int*   adj_entity   = (const int*)  d_in[1];
    const int*   adj_relation = (const int*)  d_in[2];
    const float* E            = (const float*)d_in[3];
    const float* R            = (const float*)d_in[4];
    const float* att_w1       = (const float*)d_in[5];
    const float* att_w2       = (const float*)d_in[6];
    const float* att_w3       = (const float*)d_in[7];
    const float* wx_w         = (const float*)d_in[8];
    const float* wx_b         = (const float*)d_in[9];
    const float* wc_w         = (const float*)d_in[10];
    const float* wc_b         = (const float*)d_in[11];
    float* out = (float*)d_out;

    prep_kernel<<<3126, 256>>>(E, R, att_w1);
    kgan_main_kernel<<<BSZ, 256>>>(entity_idx, adj_entity, adj_relation, E,
                                   att_w1, att_w2, att_w3,
                                   wx_w, wx_b, wc_w, wc_b, out);
}

// round 3
// speedup vs baseline: 1.7309x; 1.7309x over previous
#include <cuda_runtime.h>
#include <math.h>

#define N_ENT 100000
#define N_REL 64
#define EDIM  64
#define KN    32
#define BSZ   1024
#define SLOPE 0.2f

// Scratch (device globals; no allocation allowed)
__device__ float g_scale[N_ENT];                    // per-row normalization scale (400 KB)
__device__ __align__(16) float g_RwT[EDIM * N_REL]; // [f][r] = sum_e Rn[r][e] * att_w1[f][64+e]

// ---------------------------------------------------------------------------
// Fused prep kernel:
//   blocks [0, 3125): per-row scale of E — 8 threads/row, float4 loads
//   block  3125      : Rn = normalize(R); g_RwT[f][r] = Rn[r]·att_w1[f][64:]
// ---------------------------------------------------------------------------
__global__ void prep_kernel(const float* __restrict__ E,
                            const float* __restrict__ R,
                            const float* __restrict__ att_w1) {
    const int tid = threadIdx.x;  // 256
    if (blockIdx.x < 3125) {
        const int row  = blockIdx.x * 32 + (tid >> 3);
        const int part = tid & 7;
        const float4* Ev = reinterpret_cast<const float4*>(E + row * 64);
        float4 a = Ev[part * 2], b2 = Ev[part * 2 + 1];
        float ss = a.x*a.x + a.y*a.y + a.z*a.z + a.w*a.w
                 + b2.x*b2.x + b2.y*b2.y + b2.z*b2.z + b2.w*b2.w;
        ss += __shfl_xor_sync(0xffffffffu, ss, 4, 8);
        ss += __shfl_xor_sync(0xffffffffu, ss, 2, 8);
        ss += __shfl_xor_sync(0xffffffffu, ss, 1, 8);
        if (part == 0) {
            float n = sqrtf(ss);
            g_scale[row] = (n > 1.0f) ? (1.0f / (n + 1e-7f)) : 1.0f;
        }
        return;
    }
    // ---- prep Rw (single block) ----
    __shared__ __align__(16) float sRn[N_REL * EDIM];
    __shared__ float sScale[N_REL];
    for (int i = tid; i < N_REL * EDIM; i += 256) sRn[i] = R[i];
    __syncthreads();
    if (tid < N_REL) {
        const float4* rv = reinterpret_cast<const float4*>(sRn + tid * EDIM);
        float ss = 0.f;
        #pragma unroll
        for (int e4 = 0; e4 < 16; e4++) {
            float4 v = rv[e4];
            ss += v.x*v.x + v.y*v.y + v.z*v.z + v.w*v.w;
        }
        float n = sqrtf(ss);
        sScale[tid] = (n > 1.0f) ? (1.0f / (n + 1e-7f)) : 1.0f;
    }
    __syncthreads();
    for (int i = tid; i < N_REL * EDIM; i += 256) sRn[i] *= sScale[i >> 6];
    __syncthreads();
    for (int i = tid; i < EDIM * N_REL; i += 256) {
        int f = i >> 6, r = i & 63;
        const float4* w  = reinterpret_cast<const float4*>(att_w1 + f * 128 + 64);
        const float4* rn = reinterpret_cast<const float4*>(sRn + r * 64);
        float a0 = 0.f, a1 = 0.f;
        #pragma unroll
        for (int e4 = 0; e4 < 16; e4 += 2) {
            float4 rv = rn[e4],     wv = w[e4];
            float4 rw = rn[e4 + 1], ww = w[e4 + 1];
            a0 += rv.x*wv.x + rv.y*wv.y + rv.z*wv.z + rv.w*wv.w;
            a1 += rw.x*ww.x + rw.y*ww.y + rw.z*ww.z + rw.w*ww.w;
        }
        g_RwT[i] = a0 + a1;  // [f][r]
    }
}

// ---------------------------------------------------------------------------
// Main kernel: one block per batch element, 256 threads, 4 blocks/SM
// ---------------------------------------------------------------------------
__global__ __launch_bounds__(256, 4) void kgan_main_kernel(
    const int*   __restrict__ entity_idx,
    const int*   __restrict__ adj_entity,
    const int*   __restrict__ adj_relation,
    const float* __restrict__ E,
    const float* __restrict__ att_w1,
    const float* __restrict__ att_w2,
    const float* __restrict__ att_w3,
    const float* __restrict__ wx_w,
    const float* __restrict__ wx_b,
    const float* __restrict__ wc_w,
    const float* __restrict__ wc_b,
    float*       __restrict__ out)
{
    __shared__ __align__(16) float sRwT[64 * 64];   // [f][r]
    __shared__ __align__(16) float sW2 [64 * 64];   // permuted: slot g*16 + j*2 + h (float4 units)
    __shared__ float sw3[64];
    __shared__ float sh[64], shsum[64], sbh1[64], sbh2[64];
    __shared__ int   sEnt1[32], sRel1[32];
    __shared__ float sScale1[32];
    __shared__ float sA[96];                        // attention pre-activations
    __shared__ float sWk[32], sWks[32], sE2[64];
    __shared__ int   sPacked[1024];                 // ei | (ri<<17)
    __shared__ float sWt[1024];                     // e(rel)*scale(ent)
    __shared__ __align__(16) float2 sAggP2[8 * 32]; // per-warp hop2 partial agg
    __shared__ float sSP[8];
    __shared__ float sAgg1[64], sAgg2[64], sV1[64], sV2[64];

    const int tid  = threadIdx.x;
    const int b    = blockIdx.x;
    const int lane = tid & 31;
    const int warp = tid >> 5;

    // ================= phase A: weight tables + level-1 indices ============
    {
        const float4* Rs = reinterpret_cast<const float4*>(g_RwT);
        float4*       Rd = reinterpret_cast<float4*>(sRwT);
        const float4* Ws = reinterpret_cast<const float4*>(att_w2);
        float4*       Wd = reinterpret_cast<float4*>(sW2);
        #pragma unroll
        for (int q = 0; q < 4; q++) {
            int i = tid + q * 256;
            Rd[i] = Rs[i];
            int g = i >> 4, i4 = i & 15;           // src: row g, float4 i4 (f = i4*4..)
            Wd[g * 16 + ((i4 & 7) << 1) + (i4 >> 3)] = Ws[i];  // interleave f-halves
        }
    }
    if (tid < 64) sw3[tid] = att_w3[tid];
    const int eidx = entity_idx[b];
    if (tid < 32) {
        int e1 = adj_entity[eidx * KN + tid];
        sEnt1[tid]   = e1;
        sRel1[tid]   = adj_relation[eidx * KN + tid];
        sScale1[tid] = g_scale[e1];
    }
    if (tid < 64) sh[tid] = E[eidx * 64 + tid] * g_scale[eidx];
    __syncthreads();

    // ====== phase B: stage hop-2 adjacency (packed) + hsum =================
    #pragma unroll
    for (int q = 0; q < 4; q++) {
        int p  = tid + q * 256;
        int n1 = p >> 5, k = p & 31;
        int base = sEnt1[n1] * KN;
        int ei = adj_entity[base + k];
        int ri = adj_relation[base + k];
        sPacked[p] = ei | (ri << 17);
    }
    if (tid < 64) {
        float s = 0.f;
        #pragma unroll 8
        for (int k = 0; k < 32; k++)
            s += sScale1[k] * E[sEnt1[k] * 64 + tid];
        shsum[tid] = s;
    }
    __syncthreads();

    // ====== phase C: bh1 = h @ w1h^T, bh2 = hsum @ w1h^T ===================
    if (tid < 128) {
        int f = tid & 63;
        const float*  src = (tid < 64) ? sh : shsum;
        const float4* w   = reinterpret_cast<const float4*>(att_w1 + f * 128);
        float a0 = 0.f, a1 = 0.f;
        #pragma unroll
        for (int e4 = 0; e4 < 16; e4 += 2) {
            float4 wv = w[e4], ww = w[e4 + 1];
            a0 += wv.x * src[e4*4]   + wv.y * src[e4*4+1]
                + wv.z * src[e4*4+2] + wv.w * src[e4*4+3];
            a1 += ww.x * src[e4*4+4] + ww.y * src[e4*4+5]
                + ww.z * src[e4*4+6] + ww.w * src[e4*4+7];
        }
        if (tid < 64) sbh1[f] = a0 + a1; else sbh2[f] = a0 + a1;
    }
    __syncthreads();

    // ====== stage 7: attention tasks (96 tasks x 2 f-halves = 192 threads) =
    // task < 32: hop1 neighbor k (r = rel1[k], bh1); task in [32,96): hop2 rel r-32 (bh2)
    if (tid < 192) {
        const int task = tid >> 1;
        const int fh   = tid & 1;
        const float* bh = (task < 32) ? sbh1 : sbh2;
        const int    r  = (task < 32) ? sRel1[task] : (task - 32);

        float hid[32];
        #pragma unroll
        for (int j = 0; j < 8; j++) {
            #pragma unroll
            for (int c = 0; c < 4; c++) {
                int f = fh * 32 + j * 4 + c;
                hid[j * 4 + c] = fmaxf(bh[f] + sRwT[f * 64 + r], 0.0f);
            }
        }

        const float4* w2 = reinterpret_cast<const float4*>(sW2);
        float a = 0.0f;
        #pragma unroll
        for (int gb = 0; gb < 64; gb += 8) {
            float dp[8];
            #pragma unroll
            for (int u = 0; u < 8; u++) {
                const int g = gb + u;
                float d0 = 0.f, d1 = 0.f;
                #pragma unroll
                for (int j = 0; j < 8; j += 2) {
                    float4 wa = w2[g * 16 + j * 2 + fh];
                    float4 wb = w2[g * 16 + (j + 1) * 2 + fh];
                    d0 += wa.x * hid[j*4]   + wa.y * hid[j*4+1]
                        + wa.z * hid[j*4+2] + wa.w * hid[j*4+3];
                    d1 += wb.x * hid[j*4+4] + wb.y * hid[j*4+5]
                        + wb.z * hid[j*4+6] + wb.w * hid[j*4+7];
                }
                dp[u] = d0 + d1;
            }
            #pragma unroll
            for (int u = 0; u < 8; u++)
                dp[u] += __shfl_xor_sync(0xffffffffu, dp[u], 1);
            #pragma unroll
            for (int u = 0; u < 8; u++)
                a += sw3[gb + u] * fmaxf(dp[u], 0.0f);
        }
        if (fh == 0) sA[task] = a;
    }
    __syncthreads();

    // ====== exp(sigmoid(a)) tables =========================================
    if (tid < 96) {
        float e = expf(1.0f / (1.0f + expf(-sA[tid])));
        if (tid < 32) { sWk[tid] = e; sWks[tid] = e * sScale1[tid]; }
        else          sE2[tid - 32] = e;
    }
    __syncthreads();

    // ====== hop-2 pair weights + softmax denominator =======================
    float esum = 0.f;
    #pragma unroll
    for (int q = 0; q < 4; q++) {
        int p  = tid + q * 256;
        int pk = sPacked[p];
        int ei = pk & 0x1FFFF;
        int ri = pk >> 17;
        float e = sE2[ri];
        esum  += e;
        sWt[p] = e * g_scale[ei];
    }
    #pragma unroll
    for (int o = 16; o > 0; o >>= 1) esum += __shfl_xor_sync(0xffffffffu, esum, o);
    if (lane == 0) sSP[warp] = esum;
    __syncthreads();

    // ====== hop-2 gather: warp handles 128 pairs, lanes split feature dim ==
    {
        float accx = 0.f, accy = 0.f;
        const float2* E2 = reinterpret_cast<const float2*>(E);
        const int pbase = warp * 128;
        #pragma unroll 8
        for (int t = 0; t < 128; t++) {
            int   pk = sPacked[pbase + t];   // broadcast LDS
            float wt = sWt[pbase + t];       // broadcast LDS
            int  idx = pk & 0x1FFFF;
            float2 v = E2[idx * 32 + lane];
            accx += wt * v.x;
            accy += wt * v.y;
        }
        sAggP2[warp * 32 + lane] = make_float2(accx, accy);
    }
    // hop-1 aggregation (same threads, independent data)
    if (tid < 64) {
        float s1 = 0.f, acc = 0.f;
        #pragma unroll
        for (int k = 0; k < 32; k++) s1 += sWk[k];
        #pragma unroll 8
        for (int k = 0; k < 32; k++)
            acc += sWks[k] * E[sEnt1[k] * 64 + tid];
        sAgg1[tid] = acc / s1;
    }
    __syncthreads();

    // ====== combine hop-2 partials =========================================
    if (tid < 64) {
        const float* aggp = reinterpret_cast<const float*>(sAggP2);
        float s2 = 0.f;
        #pragma unroll
        for (int w = 0; w < 8; w++) s2 += sSP[w];
        float acc = 0.f;
        #pragma unroll
        for (int w = 0; w < 8; w++) acc += aggp[w * 64 + tid];
        sAgg2[tid] = acc / s2;
    }
    __syncthreads();

    // ====== v1/v2 = leaky(agg @ wx_w^T + wx_b) (fused, wx row loaded once) =
    if (tid < 64) {
        const float4* w = reinterpret_cast<const float4*>(wx_w + tid * 64);
        float a1 = wx_b[tid], a2 = a1;
        #pragma unroll
        for (int e4 = 0; e4 < 16; e4++) {
            float4 wv = w[e4];
            a1 += wv.x * sAgg1[e4*4]   + wv.y * sAgg1[e4*4+1]
                + wv.z * sAgg1[e4*4+2] + wv.w * sAgg1[e4*4+3];
            a2 += wv.x * sAgg2[e4*4]   + wv.y * sAgg2[e4*4+1]
                + wv.z * sAgg2[e4*4+2] + wv.w * sAgg2[e4*4+3];
        }
        sV1[tid] = (a1 >= 0.f) ? a1 : SLOPE * a1;
        sV2[tid] = (a2 >= 0.f) ? a2 : SLOPE * a2;
    }
    __syncthreads();

    // ====== emb1/emb2 = leaky([x, v] @ wc_w^T + wc_b) (fused) + h out ======
    if (tid < 64) {
        const float4* w = reinterpret_cast<const float4*>(wc_w + tid * 128);
        float a1 = wc_b[tid], a2 = a1;
        #pragma unroll
        for (int e4 = 0; e4 < 16; e4++) {
            float4 wv = w[e4];
            a1 += wv.x * sh[e4*4]      + wv.y * sh[e4*4+1]
                + wv.z * sh[e4*4+2]    + wv.w * sh[e4*4+3];
            a2 += wv.x * shsum[e4*4]   + wv.y * shsum[e4*4+1]
                + wv.z * shsum[e4*4+2] + wv.w * shsum[e4*4+3];
        }
        #pragma unroll
        for (int e4 = 0; e4 < 16; e4++) {
            float4 wv = w[16 + e4];
            a1 += wv.x * sV1[e4*4]   + wv.y * sV1[e4*4+1]
                + wv.z * sV1[e4*4+2] + wv.w * sV1[e4*4+3];
            a2 += wv.x * sV2[e4*4]   + wv.y * sV2[e4*4+1]
                + wv.z * sV2[e4*4+2] + wv.w * sV2[e4*4+3];
        }
        out[b * 192 + 64 + tid]  = (a1 >= 0.f) ? a1 : SLOPE * a1;
        out[b * 192 + tid]       = (a2 >= 0.f) ? a2 : SLOPE * a2;
        out[b * 192 + 128 + tid] = sh[tid];
    }
}

extern "C" void kernel_launch(void* const* d_in, const int* in_sizes, int n_in,
                              void* d_out, int out_size) {
    const int*   entity_idx   = (const int*)  d_in[0];
    const int*   adj_entity   = (const int*)  d_in[1];
    const int*   adj_relation = (const int*)  d_in[2];
    const float* E            = (const float*)d_in[3];
    const float* R            = (const float*)d_in[4];
    const float* att_w1       = (const float*)d_in[5];
    const float* att_w2       = (const float*)d_in[6];
    const float* att_w3       = (const float*)d_in[7];
    const float* wx_w         = (const float*)d_in[8];
    const float* wx_b         = (const float*)d_in[9];
    const float* wc_w         = (const float*)d_in[10];
    const float* wc_b         = (const float*)d_in[11];
    float* out = (float*)d_out;

    prep_kernel<<<3126, 256>>>(E, R, att_w1);
    kgan_main_kernel<<<BSZ, 256>>>(entity_idx, adj_entity, adj_relation, E,
                                   att_w1, att_w2, att_w3,
                                   wx_w, wx_b, wc_w, wc_b, out);
}